// round 1
// baseline (speedup 1.0000x reference)
#include <cuda_runtime.h>
#include <math.h>

#define D_DIM 1024
#define F_DIM 4096
#define NHEADS 16
#define HD 64

// ---------------- scratch (no cudaMalloc allowed) ----------------
__device__ float g_y   [4096u * 1024u];
__device__ float g_q   [4096u * 1024u];
__device__ float g_k   [4096u * 1024u];
__device__ float g_v   [4096u * 1024u];
__device__ float g_attn[4096u * 1024u];
__device__ float g_h   [4096u * 1024u];
__device__ float g_y2  [4096u * 1024u];
__device__ float g_ffn [4096u * 4096u];

// ---------------- srmsnorm: F.normalize(x,-1)*sqrt(D) ----------------
// one block per row, D=1024, 256 threads -> exactly one float4 per thread
__global__ __launch_bounds__(256)
void srmsnorm_kernel(const float* __restrict__ x, float* __restrict__ y) {
    const int row = blockIdx.x;
    const float4* xr = (const float4*)(x + (size_t)row * D_DIM);
    float4 v = xr[threadIdx.x];
    float ss = v.x * v.x + v.y * v.y + v.z * v.z + v.w * v.w;
    #pragma unroll
    for (int o = 16; o > 0; o >>= 1) ss += __shfl_xor_sync(0xffffffffu, ss, o);
    __shared__ float ws[8];
    if ((threadIdx.x & 31) == 0) ws[threadIdx.x >> 5] = ss;
    __syncthreads();
    float tot = ws[0] + ws[1] + ws[2] + ws[3] + ws[4] + ws[5] + ws[6] + ws[7];
    float s = 32.0f / fmaxf(sqrtf(tot), 1e-12f);   // sqrt(1024)=32
    float4* yr = (float4*)(y + (size_t)row * D_DIM);
    v.x *= s; v.y *= s; v.z *= s; v.w *= s;
    yr[threadIdx.x] = v;
}

// ---------------- gelu (tanh approximation, matches jax approximate=True) ---
__device__ __forceinline__ float gelu_tanh(float x) {
    float x3 = x * x * x;
    float t = tanhf(0.7978845608028654f * (x + 0.044715f * x3));
    return 0.5f * x * (1.0f + t);
}

// ---------------- SGEMM 128x128x8, 256 thr, 8x8 microtile -------------------
// C[M,N] = A[M,K] @ B[K,N]   (row-major). All dims multiples of 128/8.
// EPI: 0 = none, 1 = gelu, 2 = add residual R
template<int EPI>
__global__ __launch_bounds__(256)
void sgemm128(const float* __restrict__ A, const float* __restrict__ B,
              const float* __restrict__ R, float* __restrict__ C,
              int N, int K) {
    __shared__ float As[8][128];
    __shared__ float Bs[8][128];
    const int tid  = threadIdx.x;
    const int row0 = blockIdx.y * 128;
    const int col0 = blockIdx.x * 128;
    const int tx = tid & 15, ty = tid >> 4;
    const int ar = tid >> 1,  ac = (tid & 1) * 4;   // A tile: 128 rows x 8 cols
    const int br = tid >> 5,  bc = (tid & 31) * 4;  // B tile: 8 rows x 128 cols

    const float* Ap = A + (size_t)(row0 + ar) * K + ac;
    const float* Bp = B + (size_t)br * N + col0 + bc;

    float acc[8][8];
    #pragma unroll
    for (int i = 0; i < 8; ++i)
        #pragma unroll
        for (int j = 0; j < 8; ++j) acc[i][j] = 0.f;

    for (int k0 = 0; k0 < K; k0 += 8) {
        float4 av = *(const float4*)(Ap + k0);
        float4 bv = *(const float4*)(Bp + (size_t)k0 * N);
        As[ac + 0][ar] = av.x;
        As[ac + 1][ar] = av.y;
        As[ac + 2][ar] = av.z;
        As[ac + 3][ar] = av.w;
        *(float4*)&Bs[br][bc] = bv;
        __syncthreads();
        #pragma unroll
        for (int kk = 0; kk < 8; ++kk) {
            float a[8], b[8];
            *(float4*)&a[0] = *(const float4*)&As[kk][ty * 8];
            *(float4*)&a[4] = *(const float4*)&As[kk][ty * 8 + 4];
            *(float4*)&b[0] = *(const float4*)&Bs[kk][tx * 8];
            *(float4*)&b[4] = *(const float4*)&Bs[kk][tx * 8 + 4];
            #pragma unroll
            for (int i = 0; i < 8; ++i)
                #pragma unroll
                for (int j = 0; j < 8; ++j)
                    acc[i][j] = fmaf(a[i], b[j], acc[i][j]);
        }
        __syncthreads();
    }

    #pragma unroll
    for (int i = 0; i < 8; ++i) {
        size_t roff = (size_t)(row0 + ty * 8 + i) * N + col0 + tx * 8;
        #pragma unroll
        for (int j4 = 0; j4 < 8; j4 += 4) {
            float4 o;
            o.x = acc[i][j4 + 0]; o.y = acc[i][j4 + 1];
            o.z = acc[i][j4 + 2]; o.w = acc[i][j4 + 3];
            if (EPI == 1) {
                o.x = gelu_tanh(o.x); o.y = gelu_tanh(o.y);
                o.z = gelu_tanh(o.z); o.w = gelu_tanh(o.w);
            }
            if (EPI == 2) {
                float4 r = *(const float4*)(R + roff + j4);
                o.x += r.x; o.y += r.y; o.z += r.z; o.w += r.w;
            }
            *(float4*)(C + roff + j4) = o;
        }
    }
}

// ---------------- causal flash attention ------------------------------------
// grid (S/128, NHEADS, B), 128 threads, 1 thread = 1 query row.
// q/o rows live in registers (hd=64). KV tiles of 64 rows staged in smem.
// Online softmax processed in chunks of 8 to amortize o-rescale.
__global__ __launch_bounds__(128)
void flash_attn(const float* __restrict__ Q, const float* __restrict__ K,
                const float* __restrict__ V, float* __restrict__ O, int S) {
    __shared__ float4 Ks[64][16];
    __shared__ float4 Vs[64][16];
    const int b = blockIdx.z, h = blockIdx.y;
    const int qi = blockIdx.x * 128 + threadIdx.x;
    const size_t base = ((size_t)b * S) * D_DIM + (size_t)h * HD;

    const float4* qp = (const float4*)(Q + base + (size_t)qi * D_DIM);
    float4 q4[16];
    #pragma unroll
    for (int t = 0; t < 16; ++t) q4[t] = qp[t];

    float4 o4[16];
    #pragma unroll
    for (int t = 0; t < 16; ++t) o4[t] = make_float4(0.f, 0.f, 0.f, 0.f);

    float m = -1e30f, l = 0.f;
    const int ntiles = blockIdx.x * 2 + 2;  // causal: tiles up to this q-block

    for (int tile = 0; tile < ntiles; ++tile) {
        const int j0 = tile * 64;
        __syncthreads();
        #pragma unroll
        for (int i = 0; i < 8; ++i) {
            int f = i * 128 + threadIdx.x;     // 0..1023 float4 slots
            int r = f >> 4, c = f & 15;
            Ks[r][c] = *(const float4*)(K + base + (size_t)(j0 + r) * D_DIM + c * 4);
            Vs[r][c] = *(const float4*)(V + base + (size_t)(j0 + r) * D_DIM + c * 4);
        }
        __syncthreads();

        for (int jj = 0; jj < 64; jj += 8) {
            if (j0 + jj > qi) break;           // fully masked chunk
            float p8[8];
            float mloc = m;
            #pragma unroll
            for (int e = 0; e < 8; ++e) {
                const int jl = jj + e;
                float s = 0.f;
                #pragma unroll
                for (int t = 0; t < 16; ++t) {
                    float4 kk = Ks[jl][t];
                    s = fmaf(q4[t].x, kk.x, s);
                    s = fmaf(q4[t].y, kk.y, s);
                    s = fmaf(q4[t].z, kk.z, s);
                    s = fmaf(q4[t].w, kk.w, s);
                }
                s *= 0.125f;                   // 1/sqrt(64)
                if (j0 + jl > qi) s = -1e30f;  // causal mask
                p8[e] = s;
                mloc = fmaxf(mloc, s);
            }
            float alpha = __expf(m - mloc);
            m = mloc;
            float psum = 0.f;
            #pragma unroll
            for (int e = 0; e < 8; ++e) { p8[e] = __expf(p8[e] - m); psum += p8[e]; }
            l = l * alpha + psum;
            #pragma unroll
            for (int t = 0; t < 16; ++t) {
                float4 a = o4[t];
                a.x *= alpha; a.y *= alpha; a.z *= alpha; a.w *= alpha;
                #pragma unroll
                for (int e = 0; e < 8; ++e) {
                    float4 vv = Vs[jj + e][t];
                    float p = p8[e];
                    a.x = fmaf(p, vv.x, a.x);
                    a.y = fmaf(p, vv.y, a.y);
                    a.z = fmaf(p, vv.z, a.z);
                    a.w = fmaf(p, vv.w, a.w);
                }
                o4[t] = a;
            }
        }
    }

    const float inv = 1.0f / l;
    float4* op = (float4*)(O + base + (size_t)qi * D_DIM);
    #pragma unroll
    for (int t = 0; t < 16; ++t) {
        float4 a = o4[t];
        a.x *= inv; a.y *= inv; a.z *= inv; a.w *= inv;
        op[t] = a;
    }
}

// ---------------- launch ----------------------------------------------------
extern "C" void kernel_launch(void* const* d_in, const int* in_sizes, int n_in,
                              void* d_out, int out_size) {
    const float* x     = (const float*)d_in[0];
    const float* wq    = (const float*)d_in[1];
    const float* wk    = (const float*)d_in[2];
    const float* wv    = (const float*)d_in[3];
    const float* wo    = (const float*)d_in[4];
    const float* w_in  = (const float*)d_in[5];
    const float* w_out = (const float*)d_in[6];
    float* out = (float*)d_out;

    const int Mtot = in_sizes[0] / D_DIM;   // B*S = 4096
    const int B = 2;
    const int S = Mtot / B;                 // 2048

    float *y, *q, *k, *v, *attn, *h, *y2, *ffn;
    cudaGetSymbolAddress((void**)&y,    g_y);
    cudaGetSymbolAddress((void**)&q,    g_q);
    cudaGetSymbolAddress((void**)&k,    g_k);
    cudaGetSymbolAddress((void**)&v,    g_v);
    cudaGetSymbolAddress((void**)&attn, g_attn);
    cudaGetSymbolAddress((void**)&h,    g_h);
    cudaGetSymbolAddress((void**)&y2,   g_y2);
    cudaGetSymbolAddress((void**)&ffn,  g_ffn);

    // 1. y = srmsnorm(x)
    srmsnorm_kernel<<<Mtot, 256>>>(x, y);

    // 2. q,k,v = y @ {wq,wk,wv}
    dim3 gD(D_DIM / 128, Mtot / 128);       // (8, 32)
    sgemm128<0><<<gD, 256>>>(y, wq, nullptr, q, D_DIM, D_DIM);
    sgemm128<0><<<gD, 256>>>(y, wk, nullptr, k, D_DIM, D_DIM);
    sgemm128<0><<<gD, 256>>>(y, wv, nullptr, v, D_DIM, D_DIM);

    // 3. causal attention
    dim3 ga(S / 128, NHEADS, B);            // (16, 16, 2)
    flash_attn<<<ga, 128>>>(q, k, v, attn, S);

    // 4. h = attn @ wo + x
    sgemm128<2><<<gD, 256>>>(attn, wo, x, h, D_DIM, D_DIM);

    // 5. y2 = srmsnorm(h)
    srmsnorm_kernel<<<Mtot, 256>>>(h, y2);

    // 6. ffn = gelu(y2 @ w_in)
    dim3 gF(F_DIM / 128, Mtot / 128);       // (32, 32)
    sgemm128<1><<<gF, 256>>>(y2, w_in, nullptr, ffn, F_DIM, D_DIM);

    // 7. out = ffn @ w_out + h
    sgemm128<2><<<gD, 256>>>(ffn, w_out, h, out, D_DIM, F_DIM);
}

// round 4
// speedup vs baseline: 1.5858x; 1.5858x over previous
#include <cuda_runtime.h>
#include <cuda_bf16.h>
#include <math.h>
#include <stdint.h>

#define D_DIM 1024
#define F_DIM 4096
#define NHEADS 16
#define HD 64

// ---------------- scratch (no cudaMalloc allowed) ----------------
__device__ float g_y   [4096u * 1024u];
__device__ float g_q   [4096u * 1024u];
__device__ float g_k   [4096u * 1024u];
__device__ float g_v   [4096u * 1024u];
__device__ float g_attn[4096u * 1024u];
__device__ float g_h   [4096u * 1024u];
__device__ float g_y2  [4096u * 1024u];
__device__ float g_ffn [4096u * 4096u];
// transposed weights: wqT(1M) wkT(1M) wvT(1M) woT(1M) w_inT(4M) w_outT(4M)
__device__ float g_wt  [12u * 1024u * 1024u];

// ======================= helpers =======================
__device__ __forceinline__ uint32_t smem_u32(const void* p) {
    uint32_t a;
    asm("{ .reg .u64 t; cvta.to.shared.u64 t, %1; cvt.u32.u64 %0, t; }" : "=r"(a) : "l"(p));
    return a;
}
__device__ __forceinline__ void ldsm4(uint32_t& r0, uint32_t& r1, uint32_t& r2, uint32_t& r3,
                                      uint32_t addr) {
    asm volatile("ldmatrix.sync.aligned.m8n8.x4.shared.b16 {%0,%1,%2,%3}, [%4];"
                 : "=r"(r0), "=r"(r1), "=r"(r2), "=r"(r3) : "r"(addr));
}
__device__ __forceinline__ void mma16816(float* d, const uint32_t* a, uint32_t b0, uint32_t b1) {
    asm volatile(
        "mma.sync.aligned.m16n8k16.row.col.f32.bf16.bf16.f32 "
        "{%0,%1,%2,%3}, {%4,%5,%6,%7}, {%8,%9}, {%0,%1,%2,%3};"
        : "+f"(d[0]), "+f"(d[1]), "+f"(d[2]), "+f"(d[3])
        : "r"(a[0]), "r"(a[1]), "r"(a[2]), "r"(a[3]), "r"(b0), "r"(b1));
}
// split fp32x4 -> bf16 hi x4 (8B) + bf16 lo x4 (8B)
__device__ __forceinline__ void split4(float4 v, uint2& hi, uint2& lo) {
    __nv_bfloat162 h01 = __floats2bfloat162_rn(v.x, v.y);
    __nv_bfloat162 h23 = __floats2bfloat162_rn(v.z, v.w);
    float2 f01 = __bfloat1622float2(h01);
    float2 f23 = __bfloat1622float2(h23);
    __nv_bfloat162 l01 = __floats2bfloat162_rn(v.x - f01.x, v.y - f01.y);
    __nv_bfloat162 l23 = __floats2bfloat162_rn(v.z - f23.x, v.w - f23.y);
    hi.x = *(uint32_t*)&h01; hi.y = *(uint32_t*)&h23;
    lo.x = *(uint32_t*)&l01; lo.y = *(uint32_t*)&l23;
}

__device__ __forceinline__ float gelu_tanh(float x) {
    float x3 = x * x * x;
    float t = tanhf(0.7978845608028654f * (x + 0.044715f * x3));
    return 0.5f * x * (1.0f + t);
}

// ---------------- srmsnorm ----------------
__global__ __launch_bounds__(256)
void srmsnorm_kernel(const float* __restrict__ x, float* __restrict__ y) {
    const int row = blockIdx.x;
    const float4* xr = (const float4*)(x + (size_t)row * D_DIM);
    float4 v = xr[threadIdx.x];
    float ss = v.x * v.x + v.y * v.y + v.z * v.z + v.w * v.w;
    #pragma unroll
    for (int o = 16; o > 0; o >>= 1) ss += __shfl_xor_sync(0xffffffffu, ss, o);
    __shared__ float ws[8];
    if ((threadIdx.x & 31) == 0) ws[threadIdx.x >> 5] = ss;
    __syncthreads();
    float tot = ws[0] + ws[1] + ws[2] + ws[3] + ws[4] + ws[5] + ws[6] + ws[7];
    float s = 32.0f / fmaxf(sqrtf(tot), 1e-12f);
    float4* yr = (float4*)(y + (size_t)row * D_DIM);
    v.x *= s; v.y *= s; v.z *= s; v.w *= s;
    yr[threadIdx.x] = v;
}

// ---------------- transpose (dst[C][R] = src[R][C]^T) ----------------
__global__ __launch_bounds__(256)
void transpose_kernel(const float* __restrict__ src, float* __restrict__ dst, int R, int C) {
    __shared__ float t[32][33];
    int bx = blockIdx.x * 32, by = blockIdx.y * 32;
    #pragma unroll
    for (int j = 0; j < 32; j += 8)
        t[threadIdx.y + j][threadIdx.x] = src[(size_t)(by + threadIdx.y + j) * C + bx + threadIdx.x];
    __syncthreads();
    #pragma unroll
    for (int j = 0; j < 32; j += 8)
        dst[(size_t)(bx + threadIdx.y + j) * R + by + threadIdx.x] = t[threadIdx.x][threadIdx.y + j];
}

// ============== HMMA bf16 hi/lo split GEMM ==============
// C[M,N] = A[M,K] @ Bt[N,K]^T, fp32 in/out, ~fp32 accuracy (3-term bf16 split).
// CTA 128x128, K staged 32 fp32/stage, double-buffered smem.
// smem tile: 128 rows x 144 bytes: bf16 hi cols 0-31 (bytes 0-63), lo cols 32-63
// (bytes 64-127), 16B pad -> conflict-free ldmatrix (stride 144B).
// EPI: 0 none, 1 gelu, 2 +R
#define ASTR 144
#define TILEB (128 * ASTR)
#define GSMEM (4 * TILEB)   // 73728

template<int EPI>
__global__ __launch_bounds__(256)
void gemm_mma(const float* __restrict__ A, const float* __restrict__ Bt,
              const float* __restrict__ R, float* __restrict__ C,
              int Nd, int Kd) {
    extern __shared__ char smem[];
    const uint32_t sbase = smem_u32(smem);
    const int tid = threadIdx.x;
    const int lane = tid & 31, wid = tid >> 5;
    const int row0 = blockIdx.y * 128, col0 = blockIdx.x * 128;
    const int wm0 = (wid >> 2) * 64;   // warp grid 2(m) x 4(n)
    const int wn0 = (wid & 3) * 32;

    const uint32_t SA[2] = { sbase,             sbase + 2 * TILEB };
    const uint32_t SB[2] = { sbase + TILEB,     sbase + 3 * TILEB };

    float c[16][4];
    #pragma unroll
    for (int i = 0; i < 16; ++i)
        #pragma unroll
        for (int j = 0; j < 4; ++j) c[i][j] = 0.f;

    // global load mapping: 1024 float4 per tile, 4 per thread
    const int gr = tid >> 3;          // base row (+32 per i)
    const int gq = tid & 7;           // float4 index in row (32 floats)
    const float* Agl = A  + (size_t)(row0 + gr) * Kd + gq * 4;
    const float* Bgl = Bt + (size_t)(col0 + gr) * Kd + gq * 4;

    float4 va[4], vb[4];
    auto ldg = [&](int s) {
        const int k0 = s * 32;
        #pragma unroll
        for (int i = 0; i < 4; ++i) {
            va[i] = *(const float4*)(Agl + (size_t)(i * 32) * Kd + k0);
            vb[i] = *(const float4*)(Bgl + (size_t)(i * 32) * Kd + k0);
        }
    };
    auto sts = [&](int b) {
        char* da = smem + (b ? 2 * TILEB : 0);
        char* db = smem + (b ? 3 * TILEB : TILEB);
        #pragma unroll
        for (int i = 0; i < 4; ++i) {
            uint2 hi, lo;
            int off = (gr + i * 32) * ASTR + gq * 8;
            split4(va[i], hi, lo);
            *(uint2*)(da + off) = hi;
            *(uint2*)(da + off + 64) = lo;
            split4(vb[i], hi, lo);
            *(uint2*)(db + off) = hi;
            *(uint2*)(db + off + 64) = lo;
        }
    };

    const uint32_t lrow = (uint32_t)(lane & 15) * ASTR;
    const uint32_t lk   = (uint32_t)(lane >> 4) * 16;
    const int stages = Kd / 32;

    ldg(0); sts(0); __syncthreads();

    for (int s = 0; s < stages; ++s) {
        const int b = s & 1;
        if (s + 1 < stages) ldg(s + 1);

        const uint32_t Ab = SA[b] + lrow + lk;
        const uint32_t Bb = SB[b] + lrow + lk;
        #pragma unroll
        for (int kk = 0; kk < 2; ++kk) {
            const uint32_t kb = kk * 32;  // 16 bf16 = 32 bytes
            uint32_t ah[16], al[16], bh[8], bl[8];
            #pragma unroll
            for (int mt = 0; mt < 4; ++mt)
                ldsm4(ah[4*mt], ah[4*mt+1], ah[4*mt+2], ah[4*mt+3],
                      Ab + (uint32_t)(wm0 + mt * 16) * ASTR + kb);
            #pragma unroll
            for (int g = 0; g < 2; ++g)
                ldsm4(bh[4*g], bh[4*g+1], bh[4*g+2], bh[4*g+3],
                      Bb + (uint32_t)(wn0 + g * 16) * ASTR + kb);
            #pragma unroll
            for (int mt = 0; mt < 4; ++mt)
                #pragma unroll
                for (int nt = 0; nt < 4; ++nt) {
                    int bi = 4 * (nt >> 1) + (nt & 1);
                    mma16816(c[mt * 4 + nt], &ah[4 * mt], bh[bi], bh[bi + 2]);
                }
            #pragma unroll
            for (int mt = 0; mt < 4; ++mt)
                ldsm4(al[4*mt], al[4*mt+1], al[4*mt+2], al[4*mt+3],
                      Ab + (uint32_t)(wm0 + mt * 16) * ASTR + 64 + kb);
            #pragma unroll
            for (int mt = 0; mt < 4; ++mt)
                #pragma unroll
                for (int nt = 0; nt < 4; ++nt) {
                    int bi = 4 * (nt >> 1) + (nt & 1);
                    mma16816(c[mt * 4 + nt], &al[4 * mt], bh[bi], bh[bi + 2]);
                }
            #pragma unroll
            for (int g = 0; g < 2; ++g)
                ldsm4(bl[4*g], bl[4*g+1], bl[4*g+2], bl[4*g+3],
                      Bb + (uint32_t)(wn0 + g * 16) * ASTR + 64 + kb);
            #pragma unroll
            for (int mt = 0; mt < 4; ++mt)
                #pragma unroll
                for (int nt = 0; nt < 4; ++nt) {
                    int bi = 4 * (nt >> 1) + (nt & 1);
                    mma16816(c[mt * 4 + nt], &ah[4 * mt], bl[bi], bl[bi + 2]);
                }
        }
        __syncthreads();
        if (s + 1 < stages) { sts(b ^ 1); __syncthreads(); }
    }

    // epilogue
    const int mrow = row0 + wm0 + (lane >> 2);
    const int ncol = col0 + wn0 + (lane & 3) * 2;
    #pragma unroll
    for (int mt = 0; mt < 4; ++mt)
        #pragma unroll
        for (int nt = 0; nt < 4; ++nt) {
            const float* cc = c[mt * 4 + nt];
            const int m0 = mrow + mt * 16;
            const int n  = ncol + nt * 8;
            float2 r0 = make_float2(cc[0], cc[1]);
            float2 r1 = make_float2(cc[2], cc[3]);
            if (EPI == 1) {
                r0.x = gelu_tanh(r0.x); r0.y = gelu_tanh(r0.y);
                r1.x = gelu_tanh(r1.x); r1.y = gelu_tanh(r1.y);
            }
            if (EPI == 2) {
                float2 a0 = *(const float2*)(R + (size_t)m0 * Nd + n);
                float2 a1 = *(const float2*)(R + (size_t)(m0 + 8) * Nd + n);
                r0.x += a0.x; r0.y += a0.y;
                r1.x += a1.x; r1.y += a1.y;
            }
            *(float2*)(C + (size_t)m0 * Nd + n) = r0;
            *(float2*)(C + (size_t)(m0 + 8) * Nd + n) = r1;
        }
}

// ---------------- causal flash attention (fp32 SIMT) ----------------
__global__ __launch_bounds__(128)
void flash_attn(const float* __restrict__ Q, const float* __restrict__ K,
                const float* __restrict__ V, float* __restrict__ O, int S) {
    __shared__ float4 Ks[64][16];
    __shared__ float4 Vs[64][16];
    const int b = blockIdx.z, h = blockIdx.y;
    const int qi = blockIdx.x * 128 + threadIdx.x;
    const size_t base = ((size_t)b * S) * D_DIM + (size_t)h * HD;

    const float4* qp = (const float4*)(Q + base + (size_t)qi * D_DIM);
    float4 q4[16];
    #pragma unroll
    for (int t = 0; t < 16; ++t) q4[t] = qp[t];
    float4 o4[16];
    #pragma unroll
    for (int t = 0; t < 16; ++t) o4[t] = make_float4(0.f, 0.f, 0.f, 0.f);

    float m = -1e30f, l = 0.f;
    const int ntiles = blockIdx.x * 2 + 2;

    for (int tile = 0; tile < ntiles; ++tile) {
        const int j0 = tile * 64;
        __syncthreads();
        #pragma unroll
        for (int i = 0; i < 8; ++i) {
            int f = i * 128 + threadIdx.x;
            int r = f >> 4, c = f & 15;
            Ks[r][c] = *(const float4*)(K + base + (size_t)(j0 + r) * D_DIM + c * 4);
            Vs[r][c] = *(const float4*)(V + base + (size_t)(j0 + r) * D_DIM + c * 4);
        }
        __syncthreads();

        for (int jj = 0; jj < 64; jj += 8) {
            if (j0 + jj > qi) break;
            float p8[8];
            float mloc = m;
            #pragma unroll
            for (int e = 0; e < 8; ++e) {
                const int jl = jj + e;
                float s = 0.f;
                #pragma unroll
                for (int t = 0; t < 16; ++t) {
                    float4 kk = Ks[jl][t];
                    s = fmaf(q4[t].x, kk.x, s);
                    s = fmaf(q4[t].y, kk.y, s);
                    s = fmaf(q4[t].z, kk.z, s);
                    s = fmaf(q4[t].w, kk.w, s);
                }
                s *= 0.125f;
                if (j0 + jl > qi) s = -1e30f;
                p8[e] = s;
                mloc = fmaxf(mloc, s);
            }
            float alpha = __expf(m - mloc);
            m = mloc;
            float psum = 0.f;
            #pragma unroll
            for (int e = 0; e < 8; ++e) { p8[e] = __expf(p8[e] - m); psum += p8[e]; }
            l = l * alpha + psum;
            #pragma unroll
            for (int t = 0; t < 16; ++t) {
                float4 a = o4[t];
                a.x *= alpha; a.y *= alpha; a.z *= alpha; a.w *= alpha;
                #pragma unroll
                for (int e = 0; e < 8; ++e) {
                    float4 vv = Vs[jj + e][t];
                    float p = p8[e];
                    a.x = fmaf(p, vv.x, a.x);
                    a.y = fmaf(p, vv.y, a.y);
                    a.z = fmaf(p, vv.z, a.z);
                    a.w = fmaf(p, vv.w, a.w);
                }
                o4[t] = a;
            }
        }
    }

    const float inv = 1.0f / l;
    float4* op = (float4*)(O + base + (size_t)qi * D_DIM);
    #pragma unroll
    for (int t = 0; t < 16; ++t) {
        float4 a = o4[t];
        a.x *= inv; a.y *= inv; a.z *= inv; a.w *= inv;
        op[t] = a;
    }
}

// ---------------- launch ----------------------------------------------------
extern "C" void kernel_launch(void* const* d_in, const int* in_sizes, int n_in,
                              void* d_out, int out_size) {
    const float* x     = (const float*)d_in[0];
    const float* wq    = (const float*)d_in[1];
    const float* wk    = (const float*)d_in[2];
    const float* wv    = (const float*)d_in[3];
    const float* wo    = (const float*)d_in[4];
    const float* w_in  = (const float*)d_in[5];
    const float* w_out = (const float*)d_in[6];
    float* out = (float*)d_out;

    const int Mtot = in_sizes[0] / D_DIM;   // 4096
    const int B = 2;
    const int S = Mtot / B;                 // 2048

    float *y, *q, *k, *v, *attn, *h, *y2, *ffn, *wt;
    cudaGetSymbolAddress((void**)&y,    g_y);
    cudaGetSymbolAddress((void**)&q,    g_q);
    cudaGetSymbolAddress((void**)&k,    g_k);
    cudaGetSymbolAddress((void**)&v,    g_v);
    cudaGetSymbolAddress((void**)&attn, g_attn);
    cudaGetSymbolAddress((void**)&h,    g_h);
    cudaGetSymbolAddress((void**)&y2,   g_y2);
    cudaGetSymbolAddress((void**)&ffn,  g_ffn);
    cudaGetSymbolAddress((void**)&wt,   g_wt);

    float* wqT    = wt;
    float* wkT    = wt + 1024u * 1024u;
    float* wvT    = wt + 2u * 1024u * 1024u;
    float* woT    = wt + 3u * 1024u * 1024u;
    float* w_inT  = wt + 4u * 1024u * 1024u;   // [4096][1024]
    float* w_outT = wt + 8u * 1024u * 1024u;   // [1024][4096]

    cudaFuncSetAttribute(gemm_mma<0>, cudaFuncAttributeMaxDynamicSharedMemorySize, GSMEM);
    cudaFuncSetAttribute(gemm_mma<1>, cudaFuncAttributeMaxDynamicSharedMemorySize, GSMEM);
    cudaFuncSetAttribute(gemm_mma<2>, cudaFuncAttributeMaxDynamicSharedMemorySize, GSMEM);

    // weight transposes -> [N][K]
    dim3 tb(32, 8);
    transpose_kernel<<<dim3(1024 / 32, 1024 / 32), tb>>>(wq, wqT, 1024, 1024);
    transpose_kernel<<<dim3(1024 / 32, 1024 / 32), tb>>>(wk, wkT, 1024, 1024);
    transpose_kernel<<<dim3(1024 / 32, 1024 / 32), tb>>>(wv, wvT, 1024, 1024);
    transpose_kernel<<<dim3(1024 / 32, 1024 / 32), tb>>>(wo, woT, 1024, 1024);
    transpose_kernel<<<dim3(4096 / 32, 1024 / 32), tb>>>(w_in, w_inT, 1024, 4096);
    transpose_kernel<<<dim3(1024 / 32, 4096 / 32), tb>>>(w_out, w_outT, 4096, 1024);

    // 1. y = srmsnorm(x)
    srmsnorm_kernel<<<Mtot, 256>>>(x, y);

    // 2. q,k,v = y @ w
    dim3 gD(D_DIM / 128, Mtot / 128);        // (8, 32)
    gemm_mma<0><<<gD, 256, GSMEM>>>(y, wqT, nullptr, q, D_DIM, D_DIM);
    gemm_mma<0><<<gD, 256, GSMEM>>>(y, wkT, nullptr, k, D_DIM, D_DIM);
    gemm_mma<0><<<gD, 256, GSMEM>>>(y, wvT, nullptr, v, D_DIM, D_DIM);

    // 3. attention
    dim3 ga(S / 128, NHEADS, B);
    flash_attn<<<ga, 128>>>(q, k, v, attn, S);

    // 4. h = attn @ wo + x
    gemm_mma<2><<<gD, 256, GSMEM>>>(attn, woT, x, h, D_DIM, D_DIM);

    // 5. y2 = srmsnorm(h)
    srmsnorm_kernel<<<Mtot, 256>>>(h, y2);

    // 6. ffn = gelu(y2 @ w_in)
    dim3 gF(F_DIM / 128, Mtot / 128);        // (32, 32)
    gemm_mma<1><<<gF, 256, GSMEM>>>(y2, w_inT, nullptr, ffn, F_DIM, D_DIM);

    // 7. out = ffn @ w_out + h
    gemm_mma<2><<<gD, 256, GSMEM>>>(ffn, w_outT, h, out, D_DIM, F_DIM);
}